// round 1
// baseline (speedup 1.0000x reference)
#include <cuda_runtime.h>
#include <math.h>

#define B   128
#define L   336
#define N   321
#define E   128
#define LAT 64

// scratch: x transposed to [B, N, L]
__device__ float g_xp[B * N * L];

// -------------------- transpose x [B,L,N] -> xp [B,N,L] --------------------
__global__ void transpose_x(const float* __restrict__ x) {
    __shared__ float tile[32][33];
    const int b  = blockIdx.z;
    const int n0 = blockIdx.x * 32;
    const int l0 = blockIdx.y * 32;
#pragma unroll
    for (int i = 0; i < 32; i += 8) {
        int l = l0 + threadIdx.y + i;
        int n = n0 + threadIdx.x;
        if (l < L && n < N)
            tile[threadIdx.y + i][threadIdx.x] = x[(b * L + l) * N + n];
    }
    __syncthreads();
#pragma unroll
    for (int i = 0; i < 32; i += 8) {
        int n = n0 + threadIdx.y + i;
        int l = l0 + threadIdx.x;
        if (n < N && l < L)
            g_xp[(b * N + n) * L + l] = tile[threadIdx.x][threadIdx.y + i];
    }
}

// -------------------- fused per-channel kernel --------------------
// grid: (N, B/BM). One CTA: channel n, 64 batch rows.
// Phase A: h[64,128] = xp[64,336] @ W_embed[n][336,128] + b_embed[n]
//          h_hat = sigmoid(time_x)*h  (h_hat kept in SMEM)
// Phase B: mu/var[64,64] = h_hat @ W_mu/var[n][128,64] + b
#define BM  64
#define KT  8
#define KT2 16

__global__ __launch_bounds__(256) void fused_kernel(
    const float* __restrict__ time_x,
    const float* __restrict__ W_embed,
    const float* __restrict__ b_embed,
    const float* __restrict__ W_mu,
    const float* __restrict__ b_mu,
    const float* __restrict__ W_var,
    const float* __restrict__ b_var,
    float* __restrict__ out)
{
    const int n  = blockIdx.x;
    const int b0 = blockIdx.y * BM;
    const int tid = threadIdx.x;
    const int tx = tid & 15;   // 0..15 : column group
    const int ty = tid >> 4;   // 0..15 : row group

    __shared__ float As[KT][BM];        //  2 KB
    __shared__ float Bs[KT][E];         //  4 KB
    __shared__ float Hs[BM][E + 1];     // 33 KB (padded vs bank conflicts)
    __shared__ float Wm_s[KT2][LAT];    //  4 KB
    __shared__ float Wv_s[KT2][LAT];    //  4 KB

    float acc[4][8];
#pragma unroll
    for (int i = 0; i < 4; i++)
#pragma unroll
        for (int j = 0; j < 8; j++) acc[i][j] = 0.f;

    const float* Abase = g_xp + (b0 * N + n) * L;   // row m at + m*N*L
    const float* Bbase = W_embed + n * (L * E);

    // load index precompute
    const int a_m = tid >> 2;          // 0..63
    const int a_k = (tid & 3) * 2;     // 0,2,4,6
    const int b_k = tid >> 5;          // 0..7
    const int b_e = (tid & 31) * 4;    // 0..124

    for (int l0 = 0; l0 < L; l0 += KT) {
        float2 av = *(const float2*)(Abase + a_m * (N * L) + l0 + a_k);
        As[a_k    ][a_m] = av.x;
        As[a_k + 1][a_m] = av.y;
        *(float4*)&Bs[b_k][b_e] =
            *(const float4*)(Bbase + (l0 + b_k) * E + b_e);
        __syncthreads();
#pragma unroll
        for (int k = 0; k < KT; k++) {
            float a[4], bb[8];
#pragma unroll
            for (int i = 0; i < 4; i++) a[i] = As[k][ty * 4 + i];
#pragma unroll
            for (int j = 0; j < 8; j++) bb[j] = Bs[k][tx * 8 + j];
#pragma unroll
            for (int i = 0; i < 4; i++)
#pragma unroll
                for (int j = 0; j < 8; j++) acc[i][j] += a[i] * bb[j];
        }
        __syncthreads();
    }

    // ---- epilogue A: bias, sigmoid gate, write h & h_hat, stash h_hat ----
    float* out_h  = out;
    float* out_hh = out + B * N * E;
    const float* bemb = b_embed + n * E;
#pragma unroll
    for (int i = 0; i < 4; i++) {
        const int b = b0 + ty * 4 + i;
        const int rowoff = (b * N + n) * E;
#pragma unroll
        for (int j = 0; j < 8; j++) {
            const int e = tx * 8 + j;
            float h = acc[i][j] + bemb[e];
            float t = time_x[rowoff + e];
            float hh = h / (1.f + expf(-t));
            out_h [rowoff + e] = h;
            out_hh[rowoff + e] = hh;
            Hs[ty * 4 + i][e] = hh;
        }
    }
    __syncthreads();

    // ---- phase B: mu / var ----
    float accm[4][4], accv[4][4];
#pragma unroll
    for (int i = 0; i < 4; i++)
#pragma unroll
        for (int j = 0; j < 4; j++) { accm[i][j] = 0.f; accv[i][j] = 0.f; }

    const float* Wm = W_mu  + n * (E * LAT);
    const float* Wv = W_var + n * (E * LAT);
    const int w_e = tid >> 4;         // 0..15
    const int w_k = (tid & 15) * 4;   // 0..60

    for (int e0 = 0; e0 < E; e0 += KT2) {
        *(float4*)&Wm_s[w_e][w_k] = *(const float4*)(Wm + (e0 + w_e) * LAT + w_k);
        *(float4*)&Wv_s[w_e][w_k] = *(const float4*)(Wv + (e0 + w_e) * LAT + w_k);
        __syncthreads();
#pragma unroll
        for (int ke = 0; ke < KT2; ke++) {
            float a[4], wm[4], wv[4];
#pragma unroll
            for (int i = 0; i < 4; i++) a[i] = Hs[ty * 4 + i][e0 + ke];
#pragma unroll
            for (int j = 0; j < 4; j++) {
                wm[j] = Wm_s[ke][tx * 4 + j];
                wv[j] = Wv_s[ke][tx * 4 + j];
            }
#pragma unroll
            for (int i = 0; i < 4; i++)
#pragma unroll
                for (int j = 0; j < 4; j++) {
                    accm[i][j] += a[i] * wm[j];
                    accv[i][j] += a[i] * wv[j];
                }
        }
        __syncthreads();
    }

    float* out_mu  = out + 2 * B * N * E;
    float* out_var = out_mu + B * N * LAT;
#pragma unroll
    for (int i = 0; i < 4; i++) {
        const int b = b0 + ty * 4 + i;
        const int off = (b * N + n) * LAT;
#pragma unroll
        for (int j = 0; j < 4; j++) {
            const int k = tx * 4 + j;
            out_mu [off + k] = accm[i][j] + b_mu [n * LAT + k];
            out_var[off + k] = accv[i][j] + b_var[n * LAT + k];
        }
    }
}

extern "C" void kernel_launch(void* const* d_in, const int* in_sizes, int n_in,
                              void* d_out, int out_size) {
    const float* x       = (const float*)d_in[0];
    const float* time_x  = (const float*)d_in[1];
    const float* W_embed = (const float*)d_in[2];
    const float* b_embed = (const float*)d_in[3];
    const float* W_mu    = (const float*)d_in[4];
    const float* b_mu    = (const float*)d_in[5];
    const float* W_var   = (const float*)d_in[6];
    const float* b_var   = (const float*)d_in[7];
    float* out = (float*)d_out;

    dim3 tgrid((N + 31) / 32, (L + 31) / 32, B);
    dim3 tblock(32, 8);
    transpose_x<<<tgrid, tblock>>>(x);

    dim3 ggrid(N, B / BM);
    fused_kernel<<<ggrid, 256>>>(time_x, W_embed, b_embed,
                                 W_mu, b_mu, W_var, b_var, out);
}

// round 2
// speedup vs baseline: 1.3602x; 1.3602x over previous
#include <cuda_runtime.h>
#include <math.h>

#define B   128
#define L   336
#define N   321
#define E   128
#define LAT 64

__device__ float g_xp[B * N * L];

// -------------------- transpose x [B,L,N] -> xp [B,N,L] --------------------
__global__ void transpose_x(const float* __restrict__ x) {
    __shared__ float tile[32][33];
    const int b  = blockIdx.z;
    const int n0 = blockIdx.x * 32;
    const int l0 = blockIdx.y * 32;
#pragma unroll
    for (int i = 0; i < 32; i += 8) {
        int l = l0 + threadIdx.y + i;
        int n = n0 + threadIdx.x;
        if (l < L && n < N)
            tile[threadIdx.y + i][threadIdx.x] = x[(b * L + l) * N + n];
    }
    __syncthreads();
#pragma unroll
    for (int i = 0; i < 32; i += 8) {
        int n = n0 + threadIdx.y + i;
        int l = l0 + threadIdx.x;
        if (n < N && l < L)
            g_xp[(b * N + n) * L + l] = tile[threadIdx.x][threadIdx.y + i];
    }
}

// -------------------- fused per-channel kernel (v2) --------------------
#define BM   64
#define KT   8
#define KT2  16
#define NIT  (L / KT)   // 42

__global__ __launch_bounds__(256, 3) void fused_kernel(
    const float* __restrict__ time_x,
    const float* __restrict__ W_embed,
    const float* __restrict__ b_embed,
    const float* __restrict__ W_mu,
    const float* __restrict__ b_mu,
    const float* __restrict__ W_var,
    const float* __restrict__ b_var,
    float* __restrict__ out)
{
    const int n   = blockIdx.x;
    const int b0  = blockIdx.y * BM;
    const int tid = threadIdx.x;
    const int tx  = tid & 15;   // column group (0..15)
    const int ty  = tid >> 4;   // row group    (0..15)

    __shared__ float As[2][KT][BM];      //  4 KB
    __shared__ float Bs[2][KT][E];       //  8 KB
    __shared__ float Hs[BM][E + 4];      // 33.8 KB, +4 keeps float4 align
    __shared__ float Wm_s[KT2][LAT];     //  4 KB
    __shared__ float Wv_s[KT2][LAT];     //  4 KB

    float acc[4][8];
#pragma unroll
    for (int i = 0; i < 4; i++)
#pragma unroll
        for (int j = 0; j < 8; j++) acc[i][j] = 0.f;

    const float* Abase = g_xp + (b0 * N + n) * L;
    const float* Bbase = W_embed + n * (L * E);

    const int a_m = tid >> 2;          // 0..63
    const int a_k = (tid & 3) * 2;     // 0,2,4,6
    const int b_k = tid >> 5;          // 0..7
    const int b_e = (tid & 31) * 4;    // 0..124

    // prologue: stage tile 0
    float2 av = *(const float2*)(Abase + a_m * (N * L) + a_k);
    float4 bv = *(const float4*)(Bbase + b_k * E + b_e);
    As[0][a_k    ][a_m] = av.x;
    As[0][a_k + 1][a_m] = av.y;
    *(float4*)&Bs[0][b_k][b_e] = bv;
    __syncthreads();

    for (int it = 0; it < NIT; ++it) {
        const int cur = it & 1;
        if (it + 1 < NIT) {                       // prefetch next tile
            const int l0 = (it + 1) * KT;
            av = *(const float2*)(Abase + a_m * (N * L) + l0 + a_k);
            bv = *(const float4*)(Bbase + (l0 + b_k) * E + b_e);
        }
#pragma unroll
        for (int k = 0; k < KT; k++) {
            float4 a4  = *(const float4*)&As[cur][k][ty * 4];
            float4 b4a = *(const float4*)&Bs[cur][k][tx * 8];
            float4 b4b = *(const float4*)&Bs[cur][k][tx * 8 + 4];
            float a[4]  = {a4.x, a4.y, a4.z, a4.w};
            float bb[8] = {b4a.x, b4a.y, b4a.z, b4a.w,
                           b4b.x, b4b.y, b4b.z, b4b.w};
#pragma unroll
            for (int i = 0; i < 4; i++)
#pragma unroll
                for (int j = 0; j < 8; j++)
                    acc[i][j] += a[i] * bb[j];
        }
        if (it + 1 < NIT) {
            const int nxt = 1 - cur;
            As[nxt][a_k    ][a_m] = av.x;
            As[nxt][a_k + 1][a_m] = av.y;
            *(float4*)&Bs[nxt][b_k][b_e] = bv;
            __syncthreads();
        }
    }

    // ---- epilogue A: bias + sigmoid gate, vectorized ----
    float* out_h  = out;
    float* out_hh = out + B * N * E;
    const float4 bias_a = *(const float4*)(b_embed + n * E + tx * 8);
    const float4 bias_b = *(const float4*)(b_embed + n * E + tx * 8 + 4);
    const float bias[8] = {bias_a.x, bias_a.y, bias_a.z, bias_a.w,
                           bias_b.x, bias_b.y, bias_b.z, bias_b.w};
#pragma unroll
    for (int i = 0; i < 4; i++) {
        const int b      = b0 + ty * 4 + i;
        const int rowoff = (b * N + n) * E + tx * 8;
        const float4 t_a = *(const float4*)(time_x + rowoff);
        const float4 t_b = *(const float4*)(time_x + rowoff + 4);
        const float t[8] = {t_a.x, t_a.y, t_a.z, t_a.w,
                            t_b.x, t_b.y, t_b.z, t_b.w};
        float h[8], hh[8];
#pragma unroll
        for (int j = 0; j < 8; j++) {
            h[j]  = acc[i][j] + bias[j];
            hh[j] = h[j] / (1.f + __expf(-t[j]));
        }
        *(float4*)(out_h  + rowoff)     = make_float4(h[0], h[1], h[2], h[3]);
        *(float4*)(out_h  + rowoff + 4) = make_float4(h[4], h[5], h[6], h[7]);
        *(float4*)(out_hh + rowoff)     = make_float4(hh[0], hh[1], hh[2], hh[3]);
        *(float4*)(out_hh + rowoff + 4) = make_float4(hh[4], hh[5], hh[6], hh[7]);
        *(float4*)&Hs[ty * 4 + i][tx * 8]     = make_float4(hh[0], hh[1], hh[2], hh[3]);
        *(float4*)&Hs[ty * 4 + i][tx * 8 + 4] = make_float4(hh[4], hh[5], hh[6], hh[7]);
    }
    __syncthreads();

    // ---- phase B: mu / var GEMMs from SMEM h_hat ----
    float accm[4][4], accv[4][4];
#pragma unroll
    for (int i = 0; i < 4; i++)
#pragma unroll
        for (int j = 0; j < 4; j++) { accm[i][j] = 0.f; accv[i][j] = 0.f; }

    const float* Wm = W_mu  + n * (E * LAT);
    const float* Wv = W_var + n * (E * LAT);
    const int w_e = tid >> 4;         // 0..15
    const int w_k = (tid & 15) * 4;   // 0..60

    for (int e0 = 0; e0 < E; e0 += KT2) {
        *(float4*)&Wm_s[w_e][w_k] = *(const float4*)(Wm + (e0 + w_e) * LAT + w_k);
        *(float4*)&Wv_s[w_e][w_k] = *(const float4*)(Wv + (e0 + w_e) * LAT + w_k);
        __syncthreads();
#pragma unroll
        for (int ke = 0; ke < KT2; ke++) {
            float a[4];
#pragma unroll
            for (int i = 0; i < 4; i++) a[i] = Hs[ty * 4 + i][e0 + ke];
            const float4 wm4 = *(const float4*)&Wm_s[ke][tx * 4];
            const float4 wv4 = *(const float4*)&Wv_s[ke][tx * 4];
            const float wm[4] = {wm4.x, wm4.y, wm4.z, wm4.w};
            const float wv[4] = {wv4.x, wv4.y, wv4.z, wv4.w};
#pragma unroll
            for (int i = 0; i < 4; i++)
#pragma unroll
                for (int j = 0; j < 4; j++) {
                    accm[i][j] += a[i] * wm[j];
                    accv[i][j] += a[i] * wv[j];
                }
        }
        __syncthreads();
    }

    float* out_mu  = out + 2 * B * N * E;
    float* out_var = out_mu + B * N * LAT;
    const float4 bm4 = *(const float4*)(b_mu  + n * LAT + tx * 4);
    const float4 bv4 = *(const float4*)(b_var + n * LAT + tx * 4);
#pragma unroll
    for (int i = 0; i < 4; i++) {
        const int b   = b0 + ty * 4 + i;
        const int off = (b * N + n) * LAT + tx * 4;
        *(float4*)(out_mu + off) = make_float4(accm[i][0] + bm4.x, accm[i][1] + bm4.y,
                                               accm[i][2] + bm4.z, accm[i][3] + bm4.w);
        *(float4*)(out_var + off) = make_float4(accv[i][0] + bv4.x, accv[i][1] + bv4.y,
                                                accv[i][2] + bv4.z, accv[i][3] + bv4.w);
    }
}

extern "C" void kernel_launch(void* const* d_in, const int* in_sizes, int n_in,
                              void* d_out, int out_size) {
    const float* x       = (const float*)d_in[0];
    const float* time_x  = (const float*)d_in[1];
    const float* W_embed = (const float*)d_in[2];
    const float* b_embed = (const float*)d_in[3];
    const float* W_mu    = (const float*)d_in[4];
    const float* b_mu    = (const float*)d_in[5];
    const float* W_var   = (const float*)d_in[6];
    const float* b_var   = (const float*)d_in[7];
    float* out = (float*)d_out;

    dim3 tgrid((N + 31) / 32, (L + 31) / 32, B);
    dim3 tblock(32, 8);
    transpose_x<<<tgrid, tblock>>>(x);

    dim3 ggrid(N, B / BM);
    fused_kernel<<<ggrid, 256>>>(time_x, W_embed, b_embed,
                                 W_mu, b_mu, W_var, b_var, out);
}